// round 2
// baseline (speedup 1.0000x reference)
#include <cuda_runtime.h>
#include <math.h>

// Problem constants
#define NVOX 32768          // 32*32*32 voxels
#define NC   64             // channels
#define DP   34             // padded dim
#define GC   32             // channels per group
#define NG   2              // groups
#define NP   27             // kernel points
#define NOFF 162            // G*P*3
#define NMSK 54             // G*P
#define NJ   280            // NOFF + NMSK + NC pointwise outputs
#define VOLG (DP*DP*DP*GC)  // per-group padded volume floats = 1257728
#define PADVOL (NG*VOLG)    // 2515456 floats
#define K1_BLOCKS 1024      // k_dw grid blocks (512 x 2)

// ---- scratch (static device allocations; allowed) ----
__device__ float g_xc[NVOX*NC];      // depthwise conv out, voxel-major [v][c]
__device__ float g_xt[NVOX*NC];      // input transposed, voxel-major [v][c]
__device__ float g_xpad[PADVOL];     // padded projected volume [g][z][y][x][gc]
__device__ float g_off[NVOX*NOFF];   // offsets [v][g*81 + p*3 + comp]
__device__ float g_mask[NVOX*NMSK];  // softmaxed masks [v][g*27+p]
__device__ float g_part[K1_BLOCKS*2];// per-block (sum, sumsq)
__device__ float g_stats[2];         // mean, rstd
__device__ float g_wt[NJ*NC];        // transposed pointwise weights [j][c]

// ---------------------------------------------------------------------------
// Kernel 0: zero the padded volume (border must be zero every launch)
// ---------------------------------------------------------------------------
__global__ void k_zero() {
    int i = blockIdx.x * blockDim.x + threadIdx.x;
    int n = PADVOL / 4;
    if (i < n) reinterpret_cast<float4*>(g_xpad)[i] = make_float4(0.f, 0.f, 0.f, 0.f);
}

// ---------------------------------------------------------------------------
// Kernel 0b: transpose pointwise weights into [j][c] for vectorized loads
// ---------------------------------------------------------------------------
__global__ void k_wt(const float* __restrict__ off_w, const float* __restrict__ mask_w,
                     const float* __restrict__ inp_w) {
    int idx = blockIdx.x * 256 + threadIdx.x;
    if (idx >= NJ * NC) return;
    int j = idx >> 6, c = idx & 63;
    float v;
    if (j < NOFF)            v = off_w[c * NOFF + j];
    else if (j < NOFF + NMSK) v = mask_w[c * NMSK + (j - NOFF)];
    else                      v = inp_w[c * NC + (j - NOFF - NMSK)];
    g_wt[idx] = v;
}

// ---------------------------------------------------------------------------
// Kernel 1: depthwise 3x3x3 conv (pad 1) + transpose input, both written
// voxel-major with coalesced 128B stores via smem staging.
// grid (512, 2): blockIdx.x = 64-voxel tile, blockIdx.y = 32-channel half.
// 256 threads: warp w handles channels cbase + 4w .. +3, lanes = voxels.
// ---------------------------------------------------------------------------
__global__ void k_dw(const float* __restrict__ x, const float* __restrict__ dw_w) {
    int tid = threadIdx.x, lane = tid & 31, warp = tid >> 5;
    int vbase = blockIdx.x * 64;
    int cbase = blockIdx.y * 32;
    __shared__ float s_o[64][33];
    __shared__ float s_t[64][33];
    __shared__ float sh[8][2];

    float ls = 0.f, ls2 = 0.f;
#pragma unroll
    for (int cs = 0; cs < 4; cs++) {
        int c = cbase + warp * 4 + cs;
        const float* xs = x + c * NVOX;
        float w[27];
#pragma unroll
        for (int k = 0; k < 27; k++) w[k] = __ldg(dw_w + c * 27 + k);
#pragma unroll
        for (int vh = 0; vh < 2; vh++) {
            int vloc = vh * 32 + lane;
            int v = vbase + vloc;
            int iz = v >> 10, iy = (v >> 5) & 31, ix = v & 31;
            float acc = 0.f;
#pragma unroll
            for (int kz = 0; kz < 3; kz++) {
                int z = iz + kz - 1;
                if ((unsigned)z < 32u) {
#pragma unroll
                    for (int ky = 0; ky < 3; ky++) {
                        int y = iy + ky - 1;
                        if ((unsigned)y < 32u) {
#pragma unroll
                            for (int kx = 0; kx < 3; kx++) {
                                int xx = ix + kx - 1;
                                if ((unsigned)xx < 32u)
                                    acc = fmaf(w[kz*9 + ky*3 + kx],
                                               xs[(z << 10) + (y << 5) + xx], acc);
                            }
                        }
                    }
                }
            }
            s_o[vloc][c - cbase] = acc;
            s_t[vloc][c - cbase] = xs[v];
            ls += acc; ls2 += acc * acc;
        }
    }
    __syncthreads();

    // coalesced transposed writes: 32 consecutive channels = 128B per row chunk
#pragma unroll
    for (int k = 0; k < 8; k++) {
        int idx = k * 256 + tid;
        int vloc = idx >> 5, c = idx & 31;
        g_xc[(vbase + vloc) * NC + cbase + c] = s_o[vloc][c];
        g_xt[(vbase + vloc) * NC + cbase + c] = s_t[vloc][c];
    }

    // deterministic block reduction of (sum, sumsq)
#pragma unroll
    for (int o = 16; o > 0; o >>= 1) {
        ls  += __shfl_down_sync(0xffffffffu, ls,  o);
        ls2 += __shfl_down_sync(0xffffffffu, ls2, o);
    }
    if (lane == 0) { sh[warp][0] = ls; sh[warp][1] = ls2; }
    __syncthreads();
    if (tid == 0) {
        float S = 0.f, S2 = 0.f;
#pragma unroll
        for (int i = 0; i < 8; i++) { S += sh[i][0]; S2 += sh[i][1]; }
        int bid = blockIdx.y * gridDim.x + blockIdx.x;
        g_part[bid * 2]     = S;
        g_part[bid * 2 + 1] = S2;
    }
}

// ---------------------------------------------------------------------------
// Kernel 2: finalize mean / rstd (single block, deterministic)
// ---------------------------------------------------------------------------
__global__ void k_stats() {
    int tid = threadIdx.x;
    float s = 0.f, s2 = 0.f;
    for (int i = tid; i < K1_BLOCKS; i += 256) {
        s  += g_part[2 * i];
        s2 += g_part[2 * i + 1];
    }
#pragma unroll
    for (int o = 16; o > 0; o >>= 1) {
        s  += __shfl_down_sync(0xffffffffu, s,  o);
        s2 += __shfl_down_sync(0xffffffffu, s2, o);
    }
    __shared__ float sh[8][2];
    int lane = tid & 31, wid = tid >> 5;
    if (lane == 0) { sh[wid][0] = s; sh[wid][1] = s2; }
    __syncthreads();
    if (tid == 0) {
        float S = 0.f, S2 = 0.f;
#pragma unroll
        for (int i = 0; i < 8; i++) { S += sh[i][0]; S2 += sh[i][1]; }
        float n   = (float)(NVOX * NC);
        float mu  = S / n;
        float var = S2 / n - mu * mu;
        g_stats[0] = mu;
        g_stats[1] = rsqrtf(var + 1e-5f);
    }
}

// ---------------------------------------------------------------------------
// Kernel 3: per-voxel GN + tanh-GELU, then 3 pointwise GEMMs, fully
// vectorized: per 16 FMAs -> 4x LDS.128 (activations) + 1x LDG.128 (weights).
// 4 voxels per block, 256 threads.
// ---------------------------------------------------------------------------
__global__ void k_point(const float* __restrict__ gn_w,  const float* __restrict__ gn_b,
                        const float* __restrict__ inp_b, const float* __restrict__ off_b,
                        const float* __restrict__ mask_b) {
    int v0 = blockIdx.x * 4;
    int tid = threadIdx.x;
    __shared__ __align__(16) float s_x1[4][NC];
    __shared__ __align__(16) float s_xr[4][NC];
    __shared__ float s_m[4][NMSK];

    float mu = g_stats[0], rstd = g_stats[1];
    {
        int vv = tid >> 6, c = tid & 63;
        float xv = g_xc[(v0 + vv) * NC + c];
        float xn = (xv - mu) * rstd * gn_w[c] + gn_b[c];
        float t = tanhf(0.7978845608028654f * (xn + 0.044715f * xn * xn * xn));
        s_x1[vv][c] = 0.5f * xn * (1.f + t);
        s_xr[vv][c] = g_xt[(v0 + vv) * NC + c];
    }
    __syncthreads();

    for (int j = tid; j < NJ; j += 256) {
        float b;
        const float* src;
        if (j < NOFF)            { b = off_b[j];                src = &s_x1[0][0]; }
        else if (j < NOFF + NMSK){ b = mask_b[j - NOFF];        src = &s_x1[0][0]; }
        else                     { b = inp_b[j - NOFF - NMSK];  src = &s_xr[0][0]; }
        const float4* wr = reinterpret_cast<const float4*>(g_wt + (j << 6));
        const float4* xv = reinterpret_cast<const float4*>(src);
        float a0 = b, a1 = b, a2 = b, a3 = b;
#pragma unroll
        for (int c4 = 0; c4 < 16; c4++) {
            float4 w  = wr[c4];
            float4 q0 = xv[c4];
            float4 q1 = xv[16 + c4];
            float4 q2 = xv[32 + c4];
            float4 q3 = xv[48 + c4];
            a0 = fmaf(q0.x, w.x, a0); a0 = fmaf(q0.y, w.y, a0);
            a0 = fmaf(q0.z, w.z, a0); a0 = fmaf(q0.w, w.w, a0);
            a1 = fmaf(q1.x, w.x, a1); a1 = fmaf(q1.y, w.y, a1);
            a1 = fmaf(q1.z, w.z, a1); a1 = fmaf(q1.w, w.w, a1);
            a2 = fmaf(q2.x, w.x, a2); a2 = fmaf(q2.y, w.y, a2);
            a2 = fmaf(q2.z, w.z, a2); a2 = fmaf(q2.w, w.w, a2);
            a3 = fmaf(q3.x, w.x, a3); a3 = fmaf(q3.y, w.y, a3);
            a3 = fmaf(q3.z, w.z, a3); a3 = fmaf(q3.w, w.w, a3);
        }
        if (j < NOFF) {
            g_off[(v0 + 0) * NOFF + j] = a0; g_off[(v0 + 1) * NOFF + j] = a1;
            g_off[(v0 + 2) * NOFF + j] = a2; g_off[(v0 + 3) * NOFF + j] = a3;
        } else if (j < NOFF + NMSK) {
            int m = j - NOFF;
            s_m[0][m] = a0; s_m[1][m] = a1; s_m[2][m] = a2; s_m[3][m] = a3;
        } else {
            int o = j - NOFF - NMSK;
            int g = o >> 5, ch = o & 31;
            float av[4] = {a0, a1, a2, a3};
#pragma unroll
            for (int vv = 0; vv < 4; vv++) {
                int v = v0 + vv;
                int iz = v >> 10, iy = (v >> 5) & 31, ix = v & 31;
                int idx = ((((g * DP + iz + 1) * DP + iy + 1) * DP + ix + 1) << 5) + ch;
                g_xpad[idx] = av[vv];
            }
        }
    }
    __syncthreads();

    // per (voxel, group) softmax over 27 points
    if (tid < 8) {
        int vv = tid >> 1, gi = tid & 1;
        float mx = -1e30f;
#pragma unroll
        for (int p = 0; p < NP; p++) mx = fmaxf(mx, s_m[vv][gi * NP + p]);
        float s = 0.f;
#pragma unroll
        for (int p = 0; p < NP; p++) s += expf(s_m[vv][gi * NP + p] - mx);
        float inv = 1.f / s;
#pragma unroll
        for (int p = 0; p < NP; p++)
            g_mask[(v0 + vv) * NMSK + gi * NP + p] = expf(s_m[vv][gi * NP + p] - mx) * inv;
    }
}

// ---------------------------------------------------------------------------
// Kernel 4: deformable trilinear sampling + masked accumulate + output GEMM.
// 16 voxels per block, 256 threads.
// Sampling: vv = tid/16, group = (tid/8)&1, c4 = tid&7 (4 ch via float4);
// each tap: 1 LDG.128 + 4 FMA, 128B-coalesced across the 8 group lanes.
// GEMM: thread = (voxel-quad tid>>6, out-channel tid&63), weights reused x4.
// ---------------------------------------------------------------------------
__global__ void k_sample(const float* __restrict__ out_w, const float* __restrict__ out_b,
                         float* __restrict__ out) {
    int v0 = blockIdx.x * 16;
    int tid = threadIdx.x;
    __shared__ float s_off[16 * NOFF];
    __shared__ float s_m[16 * NMSK];
    __shared__ float s_acc[16][NC];

    for (int j = tid; j < 16 * NOFF; j += 256) s_off[j] = g_off[v0 * NOFF + j];
    for (int j = tid; j < 16 * NMSK; j += 256) s_m[j]   = g_mask[v0 * NMSK + j];
    __syncthreads();

    int vv = tid >> 4;
    int gi = (tid >> 3) & 1;
    int c4 = tid & 7;
    int v = v0 + vv;
    int iz = v >> 10, iy = (v >> 5) & 31, ix = v & 31;

    const float4* vol = reinterpret_cast<const float4*>(g_xpad) + gi * (VOLG / 4) + c4;
    const float* offp = s_off + vv * NOFF + gi * (NP * 3);
    const float* mp   = s_m + vv * NMSK + gi * NP;

    float4 acc = make_float4(0.f, 0.f, 0.f, 0.f);
    for (int p = 0; p < NP; p++) {
        float ox = offp[p * 3 + 0];
        float oy = offp[p * 3 + 1];
        float oz = offp[p * 3 + 2];
        // padded-volume coords: s = out_idx + k + axis_scale*0.5*off
        float sx = (float)(ix + (p % 3))       + 0.25f * ox;
        float sy = (float)(iy + ((p / 3) % 3)) + 0.5f  * oy;
        float sz = (float)(iz + (p / 9))       + 0.5f  * oz;
        float xf = floorf(sx), yf = floorf(sy), zf = floorf(sz);
        int x0 = (int)xf, y0 = (int)yf, z0 = (int)zf;
        float fx = sx - xf, fy = sy - yf, fz = sz - zf;

        float4 smp = make_float4(0.f, 0.f, 0.f, 0.f);
#pragma unroll
        for (int dz = 0; dz < 2; dz++) {
            int cz = z0 + dz;
            if ((unsigned)cz >= (unsigned)DP) continue;
            float wz = dz ? fz : 1.f - fz;
#pragma unroll
            for (int dy = 0; dy < 2; dy++) {
                int cy = y0 + dy;
                if ((unsigned)cy >= (unsigned)DP) continue;
                float wy = dy ? fy : 1.f - fy;
#pragma unroll
                for (int dx = 0; dx < 2; dx++) {
                    int cx = x0 + dx;
                    if ((unsigned)cx >= (unsigned)DP) continue;
                    float w = wz * wy * ((dx) ? fx : 1.f - fx);
                    float4 val = vol[((cz * DP + cy) * DP + cx) << 3];
                    smp.x = fmaf(w, val.x, smp.x);
                    smp.y = fmaf(w, val.y, smp.y);
                    smp.z = fmaf(w, val.z, smp.z);
                    smp.w = fmaf(w, val.w, smp.w);
                }
            }
        }
        float m = mp[p];
        acc.x = fmaf(m, smp.x, acc.x);
        acc.y = fmaf(m, smp.y, acc.y);
        acc.z = fmaf(m, smp.z, acc.z);
        acc.w = fmaf(m, smp.w, acc.w);
    }

    int ch = gi * GC + c4 * 4;
    s_acc[vv][ch + 0] = acc.x;
    s_acc[vv][ch + 1] = acc.y;
    s_acc[vv][ch + 2] = acc.z;
    s_acc[vv][ch + 3] = acc.w;
    __syncthreads();

    // output projection: 4 voxels per thread, weight reused x4
    int vq = tid >> 6;          // voxel quad 0..3
    int oc = tid & 63;          // output channel
    float b = out_b[oc];
    float o0 = b, o1 = b, o2 = b, o3 = b;
#pragma unroll 8
    for (int c = 0; c < NC; c++) {
        float w = out_w[c * NC + oc];
        o0 = fmaf(s_acc[vq * 4 + 0][c], w, o0);
        o1 = fmaf(s_acc[vq * 4 + 1][c], w, o1);
        o2 = fmaf(s_acc[vq * 4 + 2][c], w, o2);
        o3 = fmaf(s_acc[vq * 4 + 3][c], w, o3);
    }
    out[(v0 + vq * 4 + 0) * NC + oc] = o0;
    out[(v0 + vq * 4 + 1) * NC + oc] = o1;
    out[(v0 + vq * 4 + 2) * NC + oc] = o2;
    out[(v0 + vq * 4 + 3) * NC + oc] = o3;
}

// ---------------------------------------------------------------------------
extern "C" void kernel_launch(void* const* d_in, const int* in_sizes, int n_in,
                              void* d_out, int out_size) {
    const float* x      = (const float*)d_in[0];
    const float* dw_w   = (const float*)d_in[1];
    const float* gn_w   = (const float*)d_in[2];
    const float* gn_b   = (const float*)d_in[3];
    const float* inp_w  = (const float*)d_in[4];
    const float* inp_b  = (const float*)d_in[5];
    const float* off_w  = (const float*)d_in[6];
    const float* off_b  = (const float*)d_in[7];
    const float* mask_w = (const float*)d_in[8];
    const float* mask_b = (const float*)d_in[9];
    const float* out_w  = (const float*)d_in[10];
    const float* out_b  = (const float*)d_in[11];
    float* out = (float*)d_out;

    k_zero<<<(PADVOL / 4 + 255) / 256, 256>>>();
    k_wt<<<(NJ * NC + 255) / 256, 256>>>(off_w, mask_w, inp_w);
    k_dw<<<dim3(512, 2), 256>>>(x, dw_w);
    k_stats<<<1, 256>>>();
    k_point<<<NVOX / 4, 256>>>(gn_w, gn_b, inp_b, off_b, mask_b);
    k_sample<<<NVOX / 16, 256>>>(out_w, out_b, out);
}

// round 3
// speedup vs baseline: 1.1093x; 1.1093x over previous
#include <cuda_runtime.h>
#include <math.h>

// Problem constants
#define NVOX 32768          // 32*32*32 voxels
#define NC   64             // channels
#define DP   34             // padded dim
#define GC   32             // channels per group
#define NG   2              // groups
#define NP   27             // kernel points
#define NOFF 162            // G*P*3
#define NMSK 54             // G*P
#define NJ   280            // NOFF + NMSK + NC pointwise outputs
#define VOLG (DP*DP*DP*GC)  // per-group padded volume floats = 1257728
#define PADVOL (NG*VOLG)    // 2515456 floats
#define K1_BLOCKS (128*64)

// ---- scratch (static device allocations; allowed) ----
__device__ __align__(256) float g_xc[NC*NVOX];     // depthwise conv out, c-major [c][v]
__device__ __align__(256) float g_xpad[PADVOL];    // padded projected volume [g][z][y][x][gc]
__device__ __align__(256) float g_off[NOFF*NVOX];  // offsets, TRANSPOSED [j][v]
__device__ __align__(256) float g_mask[NMSK*NVOX]; // mask logits, TRANSPOSED [j][v]
__device__ float g_part[K1_BLOCKS*2];              // per-block (sum, sumsq)
__device__ float g_stats[2];                       // mean, rstd
__device__ __align__(256) float g_wt[NJ*NC];       // transposed weights [j][c]; rows: off|mask|inp

// ---------------------------------------------------------------------------
// Kernel 0: zero padded volume + build transposed weight matrix (fused)
// ---------------------------------------------------------------------------
__global__ void k_init(const float* __restrict__ off_w, const float* __restrict__ mask_w,
                       const float* __restrict__ inp_w) {
    int gid = blockIdx.x * 256 + threadIdx.x;
    if (gid < PADVOL / 4)
        reinterpret_cast<float4*>(g_xpad)[gid] = make_float4(0.f, 0.f, 0.f, 0.f);
    if (gid < NJ * NC) {
        int j = gid >> 6, c = gid & 63;
        float v;
        if (j < NOFF)             v = off_w[c * NOFF + j];
        else if (j < NOFF + NMSK) v = mask_w[c * NMSK + (j - NOFF)];
        else                      v = inp_w[c * NC + (j - NOFF - NMSK)];
        g_wt[gid] = v;
    }
}

// ---------------------------------------------------------------------------
// Kernel 1: depthwise 3x3x3 conv (pad 1), c-major output (natural coalesced),
//           + per-block sum/sumsq partials for GroupNorm(1).
// grid (128, 64): blockIdx.y = channel, 256 voxels per block
// ---------------------------------------------------------------------------
__global__ void k_dw(const float* __restrict__ x, const float* __restrict__ dw_w) {
    int c = blockIdx.y;
    int v = blockIdx.x * 256 + threadIdx.x;
    int iz = v >> 10, iy = (v >> 5) & 31, ix = v & 31;
    const float* xs = x + c * NVOX;

    float w[27];
#pragma unroll
    for (int k = 0; k < 27; k++) w[k] = __ldg(dw_w + c * 27 + k);

    float acc = 0.f;
#pragma unroll
    for (int kz = 0; kz < 3; kz++) {
        int z = iz + kz - 1;
        if ((unsigned)z < 32u) {
#pragma unroll
            for (int ky = 0; ky < 3; ky++) {
                int y = iy + ky - 1;
                if ((unsigned)y < 32u) {
#pragma unroll
                    for (int kx = 0; kx < 3; kx++) {
                        int xx = ix + kx - 1;
                        if ((unsigned)xx < 32u)
                            acc = fmaf(w[kz*9 + ky*3 + kx], xs[(z << 10) + (y << 5) + xx], acc);
                    }
                }
            }
        }
    }
    g_xc[c * NVOX + v] = acc;

    float s = acc, s2 = acc * acc;
#pragma unroll
    for (int o = 16; o > 0; o >>= 1) {
        s  += __shfl_down_sync(0xffffffffu, s,  o);
        s2 += __shfl_down_sync(0xffffffffu, s2, o);
    }
    __shared__ float sh[8][2];
    int lane = threadIdx.x & 31, wid = threadIdx.x >> 5;
    if (lane == 0) { sh[wid][0] = s; sh[wid][1] = s2; }
    __syncthreads();
    if (threadIdx.x == 0) {
        float S = 0.f, S2 = 0.f;
#pragma unroll
        for (int i = 0; i < 8; i++) { S += sh[i][0]; S2 += sh[i][1]; }
        int bid = blockIdx.y * gridDim.x + blockIdx.x;
        g_part[bid * 2]     = S;
        g_part[bid * 2 + 1] = S2;
    }
}

// ---------------------------------------------------------------------------
// Kernel 2: finalize mean / rstd (single block, deterministic)
// ---------------------------------------------------------------------------
__global__ void k_stats() {
    int tid = threadIdx.x;
    float s = 0.f, s2 = 0.f;
    for (int i = tid; i < K1_BLOCKS; i += 256) {
        float2 p = reinterpret_cast<const float2*>(g_part)[i];
        s += p.x; s2 += p.y;
    }
#pragma unroll
    for (int o = 16; o > 0; o >>= 1) {
        s  += __shfl_down_sync(0xffffffffu, s,  o);
        s2 += __shfl_down_sync(0xffffffffu, s2, o);
    }
    __shared__ float sh[8][2];
    int lane = tid & 31, wid = tid >> 5;
    if (lane == 0) { sh[wid][0] = s; sh[wid][1] = s2; }
    __syncthreads();
    if (tid == 0) {
        float S = 0.f, S2 = 0.f;
#pragma unroll
        for (int i = 0; i < 8; i++) { S += sh[i][0]; S2 += sh[i][1]; }
        float n   = (float)(NVOX * NC);
        float mu  = S / n;
        float var = S2 / n - mu * mu;
        g_stats[0] = mu;
        g_stats[1] = rsqrtf(var + 1e-5f);
    }
}

// ---------------------------------------------------------------------------
// dot of 64-reg activation vector with a broadcast weight row (16x LDG.128,
// all lanes same address -> 1 wavefront each; 64 FMA over 4 ILP chains).
// ---------------------------------------------------------------------------
__device__ __forceinline__ float dot64(const float* a, const float* w) {
    const float4* w4 = reinterpret_cast<const float4*>(w);
    float s0 = 0.f, s1 = 0.f, s2 = 0.f, s3 = 0.f;
#pragma unroll
    for (int q = 0; q < 4; q++) {
        float4 wa = __ldg(&w4[q * 4 + 0]);
        float4 wb = __ldg(&w4[q * 4 + 1]);
        float4 wc = __ldg(&w4[q * 4 + 2]);
        float4 wd = __ldg(&w4[q * 4 + 3]);
        const float* aq = a + q * 16;
        s0 = fmaf(aq[0],  wa.x, s0); s0 = fmaf(aq[1],  wa.y, s0);
        s0 = fmaf(aq[2],  wa.z, s0); s0 = fmaf(aq[3],  wa.w, s0);
        s1 = fmaf(aq[4],  wb.x, s1); s1 = fmaf(aq[5],  wb.y, s1);
        s1 = fmaf(aq[6],  wb.z, s1); s1 = fmaf(aq[7],  wb.w, s1);
        s2 = fmaf(aq[8],  wc.x, s2); s2 = fmaf(aq[9],  wc.y, s2);
        s2 = fmaf(aq[10], wc.z, s2); s2 = fmaf(aq[11], wc.w, s2);
        s3 = fmaf(aq[12], wd.x, s3); s3 = fmaf(aq[13], wd.y, s3);
        s3 = fmaf(aq[14], wd.z, s3); s3 = fmaf(aq[15], wd.w, s3);
    }
    return (s0 + s1) + (s2 + s3);
}

// ---------------------------------------------------------------------------
// Kernel 3: thread = voxel. GN + GELU into regs, then 280 dot products with
// broadcast weight rows. Outputs stored transposed ([j][v], coalesced).
// ---------------------------------------------------------------------------
__global__ void __launch_bounds__(128, 4)
k_point(const float* __restrict__ x,
        const float* __restrict__ gn_w,  const float* __restrict__ gn_b,
        const float* __restrict__ inp_b, const float* __restrict__ off_b,
        const float* __restrict__ mask_b) {
    int v = blockIdx.x * 128 + threadIdx.x;
    int iz = v >> 10, iy = (v >> 5) & 31, ix = v & 31;
    float mu = g_stats[0], rstd = g_stats[1];

    float a[64];
    // x1 = gelu(groupnorm(xc)) : per-c loads are lane-coalesced (lane = voxel)
#pragma unroll
    for (int c = 0; c < 64; c++) {
        float xv = g_xc[c * NVOX + v];
        float xn = (xv - mu) * rstd * __ldg(gn_w + c) + __ldg(gn_b + c);
        // gelu(x) = x * sigmoid(2*0.79788456*(x + 0.044715 x^3))
        float u = xn + 0.044715f * xn * xn * xn;
        float e = __expf(-1.5957691216057308f * u);
        a[c] = xn / (1.f + e);
    }

    // offsets: j rows [0, 162)
#pragma unroll 1
    for (int j = 0; j < NOFF; j++)
        g_off[j * NVOX + v] = __ldg(off_b + j) + dot64(a, g_wt + j * NC);

    // mask logits: j rows [162, 216). softmax deferred to k_sample.
#pragma unroll 1
    for (int j = 0; j < NMSK; j++)
        g_mask[j * NVOX + v] = __ldg(mask_b + j) + dot64(a, g_wt + (NOFF + j) * NC);

    // input projection: reload original x (c-major, coalesced per c)
#pragma unroll
    for (int c = 0; c < 64; c++) a[c] = x[c * NVOX + v];

#pragma unroll 1
    for (int o = 0; o < NC; o += 4) {
        float r0 = __ldg(inp_b + o + 0) + dot64(a, g_wt + (NOFF + NMSK + o + 0) * NC);
        float r1 = __ldg(inp_b + o + 1) + dot64(a, g_wt + (NOFF + NMSK + o + 1) * NC);
        float r2 = __ldg(inp_b + o + 2) + dot64(a, g_wt + (NOFF + NMSK + o + 2) * NC);
        float r3 = __ldg(inp_b + o + 3) + dot64(a, g_wt + (NOFF + NMSK + o + 3) * NC);
        int g = o >> 5, ch = o & 31;
        int idx = ((((g * DP + iz + 1) * DP + iy + 1) * DP + ix + 1) << 5) + ch;
        *reinterpret_cast<float4*>(&g_xpad[idx]) = make_float4(r0, r1, r2, r3);
    }
}

// ---------------------------------------------------------------------------
// Kernel 4: deformable trilinear sampling + masked accumulate + output GEMM.
// 16 voxels per block, 256 threads. Softmax over 27 points done in smem here.
// Sampling: vv = tid/16, group = (tid/8)&1, c4 = tid&7 (4 ch via float4);
// each tap: 1 LDG.128 + 4 FMA, 128B-coalesced across the 8 group lanes.
// ---------------------------------------------------------------------------
__global__ void k_sample(const float* __restrict__ out_w, const float* __restrict__ out_b,
                         float* __restrict__ out) {
    int v0 = blockIdx.x * 16;
    int tid = threadIdx.x;
    __shared__ float s_off[16][NOFF];
    __shared__ float s_m[16][NMSK];
    __shared__ float s_acc[16][NC];

    for (int idx = tid; idx < 16 * NOFF; idx += 256) {
        int j = idx >> 4, vloc = idx & 15;
        s_off[vloc][j] = g_off[j * NVOX + v0 + vloc];
    }
    for (int idx = tid; idx < 16 * NMSK; idx += 256) {
        int j = idx >> 4, vloc = idx & 15;
        s_m[vloc][j] = g_mask[j * NVOX + v0 + vloc];
    }
    __syncthreads();

    // per (voxel, group) softmax over 27 points
    if (tid < 32) {
        int vv = tid >> 1, gi = tid & 1;
        float* m = &s_m[vv][gi * NP];
        float mx = -1e30f;
#pragma unroll
        for (int p = 0; p < NP; p++) mx = fmaxf(mx, m[p]);
        float s = 0.f;
#pragma unroll
        for (int p = 0; p < NP; p++) { float e = __expf(m[p] - mx); m[p] = e; s += e; }
        float inv = 1.f / s;
#pragma unroll
        for (int p = 0; p < NP; p++) m[p] *= inv;
    }
    __syncthreads();

    int vv = tid >> 4;
    int gi = (tid >> 3) & 1;
    int c4 = tid & 7;
    int v = v0 + vv;
    int iz = v >> 10, iy = (v >> 5) & 31, ix = v & 31;

    const float4* vol = reinterpret_cast<const float4*>(g_xpad) + gi * (VOLG / 4) + c4;
    const float* offp = &s_off[vv][gi * (NP * 3)];
    const float* mp   = &s_m[vv][gi * NP];

    float4 acc = make_float4(0.f, 0.f, 0.f, 0.f);
    for (int p = 0; p < NP; p++) {
        float ox = offp[p * 3 + 0];
        float oy = offp[p * 3 + 1];
        float oz = offp[p * 3 + 2];
        // padded-volume coords: s = out_idx + k + axis_scale*0.5*off
        float sx = (float)(ix + (p % 3))       + 0.25f * ox;
        float sy = (float)(iy + ((p / 3) % 3)) + 0.5f  * oy;
        float sz = (float)(iz + (p / 9))       + 0.5f  * oz;
        float xf = floorf(sx), yf = floorf(sy), zf = floorf(sz);
        int x0 = (int)xf, y0 = (int)yf, z0 = (int)zf;
        float fx = sx - xf, fy = sy - yf, fz = sz - zf;

        float4 smp = make_float4(0.f, 0.f, 0.f, 0.f);
#pragma unroll
        for (int dz = 0; dz < 2; dz++) {
            int cz = z0 + dz;
            if ((unsigned)cz >= (unsigned)DP) continue;
            float wz = dz ? fz : 1.f - fz;
#pragma unroll
            for (int dy = 0; dy < 2; dy++) {
                int cy = y0 + dy;
                if ((unsigned)cy >= (unsigned)DP) continue;
                float wy = dy ? fy : 1.f - fy;
#pragma unroll
                for (int dx = 0; dx < 2; dx++) {
                    int cx = x0 + dx;
                    if ((unsigned)cx >= (unsigned)DP) continue;
                    float w = wz * wy * ((dx) ? fx : 1.f - fx);
                    float4 val = vol[((cz * DP + cy) * DP + cx) << 3];
                    smp.x = fmaf(w, val.x, smp.x);
                    smp.y = fmaf(w, val.y, smp.y);
                    smp.z = fmaf(w, val.z, smp.z);
                    smp.w = fmaf(w, val.w, smp.w);
                }
            }
        }
        float m = mp[p];
        acc.x = fmaf(m, smp.x, acc.x);
        acc.y = fmaf(m, smp.y, acc.y);
        acc.z = fmaf(m, smp.z, acc.z);
        acc.w = fmaf(m, smp.w, acc.w);
    }

    int ch = gi * GC + c4 * 4;
    s_acc[vv][ch + 0] = acc.x;
    s_acc[vv][ch + 1] = acc.y;
    s_acc[vv][ch + 2] = acc.z;
    s_acc[vv][ch + 3] = acc.w;
    __syncthreads();

    // output projection: 4 voxels per thread, weight reused x4
    int vq = tid >> 6;
    int oc = tid & 63;
    float b = __ldg(out_b + oc);
    float o0 = b, o1 = b, o2 = b, o3 = b;
#pragma unroll 8
    for (int c = 0; c < NC; c++) {
        float w = __ldg(out_w + c * NC + oc);
        o0 = fmaf(s_acc[vq * 4 + 0][c], w, o0);
        o1 = fmaf(s_acc[vq * 4 + 1][c], w, o1);
        o2 = fmaf(s_acc[vq * 4 + 2][c], w, o2);
        o3 = fmaf(s_acc[vq * 4 + 3][c], w, o3);
    }
    out[(v0 + vq * 4 + 0) * NC + oc] = o0;
    out[(v0 + vq * 4 + 1) * NC + oc] = o1;
    out[(v0 + vq * 4 + 2) * NC + oc] = o2;
    out[(v0 + vq * 4 + 3) * NC + oc] = o3;
}

// ---------------------------------------------------------------------------
extern "C" void kernel_launch(void* const* d_in, const int* in_sizes, int n_in,
                              void* d_out, int out_size) {
    const float* x      = (const float*)d_in[0];
    const float* dw_w   = (const float*)d_in[1];
    const float* gn_w   = (const float*)d_in[2];
    const float* gn_b   = (const float*)d_in[3];
    const float* inp_w  = (const float*)d_in[4];
    const float* inp_b  = (const float*)d_in[5];
    const float* off_w  = (const float*)d_in[6];
    const float* off_b  = (const float*)d_in[7];
    const float* mask_w = (const float*)d_in[8];
    const float* mask_b = (const float*)d_in[9];
    const float* out_w  = (const float*)d_in[10];
    const float* out_b  = (const float*)d_in[11];
    float* out = (float*)d_out;

    k_init<<<(PADVOL / 4 + 255) / 256, 256>>>(off_w, mask_w, inp_w);
    k_dw<<<dim3(128, 64), 256>>>(x, dw_w);
    k_stats<<<1, 256>>>();
    k_point<<<NVOX / 128, 128>>>(x, gn_w, gn_b, inp_b, off_b, mask_b);
    k_sample<<<NVOX / 16, 256>>>(out_w, out_b, out);
}

// round 4
// speedup vs baseline: 1.7159x; 1.5468x over previous
#include <cuda_runtime.h>
#include <math.h>

// Problem constants
#define NVOX 32768          // 32*32*32 voxels
#define NC   64             // channels
#define DP   34             // padded dim
#define GC   32             // channels per group
#define NG   2              // groups
#define NP   27             // kernel points
#define NOFF 162            // G*P*3
#define NMSK 54             // G*P
#define NJP  320            // padded j rows: 64 inp | 162 off | 54 mask | 40 zero
#define VOLG (DP*DP*DP*GC)  // per-group padded volume floats
#define PADVOL (NG*VOLG)
#define KDW_BLOCKS 2048     // k_dw grid (32 x 64)

// ---- scratch (static device globals; zero-initialized at module load) ----
__device__ __align__(256) float g_xc[NC*NVOX];     // depthwise conv out, c-major [c][v]
__device__ __align__(256) float g_xpad[PADVOL];    // padded projected volume [g][z][y][x][gc]
                                                   // borders: never written, stay 0
__device__ __align__(256) float g_off[NOFF*NVOX];  // offsets, transposed [j][v]
__device__ __align__(256) float g_mask[NMSK*NVOX]; // mask logits, transposed [j][v]
__device__ float g_part[KDW_BLOCKS*2];             // per-block (sum, sumsq)
__device__ float g_stats[2];                       // mean, rstd
__device__ __align__(256) float g_wtT[NC*NJP];     // weights [k][j], j-reordered+padded
__device__ float g_bias[NJP];                      // reordered bias

// ---------------------------------------------------------------------------
// Kernel 0: build reordered weight matrix [k][j] + bias
//   j in [0,64)    : inp_w column j           (A = raw x)
//   j in [64,226)  : off_w column j-64        (A = gelu(gn(xc)))
//   j in [226,280) : mask_w column j-226      (A = gelu(gn(xc)))
//   j in [280,320) : zero padding
// ---------------------------------------------------------------------------
__global__ void k_init(const float* __restrict__ inp_w, const float* __restrict__ off_w,
                       const float* __restrict__ mask_w,
                       const float* __restrict__ inp_b, const float* __restrict__ off_b,
                       const float* __restrict__ mask_b) {
    int gid = blockIdx.x * 256 + threadIdx.x;
    if (gid < NC * NJP) {
        int k = gid / NJP, j = gid - k * NJP;
        float v = 0.f;
        if (j < 64)       v = inp_w[k * NC + j];
        else if (j < 226) v = off_w[k * NOFF + (j - 64)];
        else if (j < 280) v = mask_w[k * NMSK + (j - 226)];
        g_wtT[gid] = v;
    }
    if (gid < NJP) {
        int j = gid;
        float b = 0.f;
        if (j < 64)       b = inp_b[j];
        else if (j < 226) b = off_b[j - 64];
        else if (j < 280) b = mask_b[j - 226];
        g_bias[j] = b;
    }
}

// ---------------------------------------------------------------------------
// Kernel 1: depthwise 3x3x3 conv via smem slab (3 z-slices + halo).
// grid (32, 64): blockIdx.x = z slice, blockIdx.y = channel. 256 threads.
// Each output read from smem: 27 LDS + 27 broadcast weight LDG per voxel.
// ---------------------------------------------------------------------------
__global__ void k_dw(const float* __restrict__ x, const float* __restrict__ dw_w) {
    int bz = blockIdx.x, c = blockIdx.y;
    int tid = threadIdx.x;
    __shared__ float s[3][34][34];
    __shared__ float sh[8][2];

    const float* xs = x + c * NVOX;
    // halo load: 3 slices of 34x34, borders zero
    for (int i = tid; i < 3 * 34 * 34; i += 256) {
        int sl = i / 1156;
        int rem = i - sl * 1156;
        int yy = rem / 34;
        int xx = rem - yy * 34;
        int z = bz + sl - 1, y = yy - 1, xg = xx - 1;
        float val = 0.f;
        if ((unsigned)z < 32u && (unsigned)y < 32u && (unsigned)xg < 32u)
            val = xs[(z << 10) + (y << 5) + xg];
        s[sl][yy][xx] = val;
    }
    float w[27];
#pragma unroll
    for (int k = 0; k < 27; k++) w[k] = __ldg(dw_w + c * 27 + k);
    __syncthreads();

    float ls = 0.f, ls2 = 0.f;
#pragma unroll
    for (int q = 0; q < 4; q++) {
        int vloc = q * 256 + tid;
        int iy = vloc >> 5, ix = vloc & 31;
        float acc = 0.f;
#pragma unroll
        for (int kz = 0; kz < 3; kz++)
#pragma unroll
            for (int ky = 0; ky < 3; ky++)
#pragma unroll
                for (int kx = 0; kx < 3; kx++)
                    acc = fmaf(w[kz*9 + ky*3 + kx], s[kz][iy + ky][ix + kx], acc);
        g_xc[c * NVOX + (bz << 10) + vloc] = acc;
        ls += acc; ls2 += acc * acc;
    }

    // deterministic block reduction
#pragma unroll
    for (int o = 16; o > 0; o >>= 1) {
        ls  += __shfl_down_sync(0xffffffffu, ls,  o);
        ls2 += __shfl_down_sync(0xffffffffu, ls2, o);
    }
    int lane = tid & 31, warp = tid >> 5;
    if (lane == 0) { sh[warp][0] = ls; sh[warp][1] = ls2; }
    __syncthreads();
    if (tid == 0) {
        float S = 0.f, S2 = 0.f;
#pragma unroll
        for (int i = 0; i < 8; i++) { S += sh[i][0]; S2 += sh[i][1]; }
        int bid = c * 32 + bz;
        g_part[bid * 2]     = S;
        g_part[bid * 2 + 1] = S2;
    }
}

// ---------------------------------------------------------------------------
// Kernel 2: finalize mean / rstd
// ---------------------------------------------------------------------------
__global__ void k_stats() {
    int tid = threadIdx.x;
    float s = 0.f, s2 = 0.f;
    for (int i = tid; i < KDW_BLOCKS; i += 256) {
        float2 p = reinterpret_cast<const float2*>(g_part)[i];
        s += p.x; s2 += p.y;
    }
#pragma unroll
    for (int o = 16; o > 0; o >>= 1) {
        s  += __shfl_down_sync(0xffffffffu, s,  o);
        s2 += __shfl_down_sync(0xffffffffu, s2, o);
    }
    __shared__ float sh[8][2];
    int lane = tid & 31, wid = tid >> 5;
    if (lane == 0) { sh[wid][0] = s; sh[wid][1] = s2; }
    __syncthreads();
    if (tid == 0) {
        float S = 0.f, S2 = 0.f;
#pragma unroll
        for (int i = 0; i < 8; i++) { S += sh[i][0]; S2 += sh[i][1]; }
        float n   = (float)(NVOX * NC);
        float mu  = S / n;
        float var = S2 / n - mu * mu;
        g_stats[0] = mu;
        g_stats[1] = rsqrtf(var + 1e-5f);
    }
}

// ---------------------------------------------------------------------------
// Kernel 3: tiled GEMM. C[v][j] = A[v][k] * W[k][j], M=32768, N=320, K=64.
// grid (256, 5): x = 128-voxel tile, y = 64-j tile (jt).
//   jt==0: A = raw x (c-major);  jt>=1: A = gelu(gn(g_xc)).
// 256 threads, thread tile 8 voxels x 4 j. smem A 32KB + B 16KB.
// Stores: jt==0 -> g_xpad (channel float4); else -> g_off/g_mask rows
// (voxel float4, fully coalesced).
// ---------------------------------------------------------------------------
__global__ void __launch_bounds__(256)
k_point(const float* __restrict__ x,
        const float* __restrict__ gn_w, const float* __restrict__ gn_b) {
    int jt = blockIdx.y;
    int vbase = blockIdx.x * 128;
    int tid = threadIdx.x;
    __shared__ float sA[64 * 128];
    __shared__ float sB[64 * 64];

    // stage B tile: W[k][jt*64 .. +63]
#pragma unroll
    for (int i = 0; i < 4; i++) {
        int lin = i * 1024 + tid * 4;
        int k = lin >> 6, j = lin & 63;
        *reinterpret_cast<float4*>(&sB[lin]) =
            *reinterpret_cast<const float4*>(&g_wtT[k * NJP + jt * 64 + j]);
    }
    // stage A tile
    if (jt == 0) {
#pragma unroll
        for (int i = 0; i < 8; i++) {
            int lin = i * 1024 + tid * 4;
            int k = lin >> 7, vl = lin & 127;
            *reinterpret_cast<float4*>(&sA[lin]) =
                *reinterpret_cast<const float4*>(&x[k * NVOX + vbase + vl]);
        }
    } else {
        float mu = g_stats[0], rstd = g_stats[1];
#pragma unroll
        for (int i = 0; i < 8; i++) {
            int lin = i * 1024 + tid * 4;
            int k = lin >> 7, vl = lin & 127;
            float gw = __ldg(gn_w + k) * rstd;
            float gb = __ldg(gn_b + k) - mu * gw;
            float4 xv = *reinterpret_cast<const float4*>(&g_xc[k * NVOX + vbase + vl]);
            float r[4] = {xv.x, xv.y, xv.z, xv.w};
#pragma unroll
            for (int e = 0; e < 4; e++) {
                float xn = r[e] * gw + gb;
                float u = xn + 0.044715f * xn * xn * xn;
                r[e] = xn / (1.f + __expf(-1.5957691216057308f * u));
            }
            *reinterpret_cast<float4*>(&sA[lin]) = make_float4(r[0], r[1], r[2], r[3]);
        }
    }
    __syncthreads();

    int tx = tid & 15, ty = tid >> 4;
    float acc[8][4];
#pragma unroll
    for (int i = 0; i < 8; i++)
#pragma unroll
        for (int j = 0; j < 4; j++) acc[i][j] = 0.f;

    const float4* A4 = reinterpret_cast<const float4*>(sA);
    const float4* B4 = reinterpret_cast<const float4*>(sB);
#pragma unroll 8
    for (int k = 0; k < 64; k++) {
        float4 a0 = A4[k * 32 + tx];
        float4 a1 = A4[k * 32 + 16 + tx];
        float4 b  = B4[k * 16 + ty];
        float av[8] = {a0.x, a0.y, a0.z, a0.w, a1.x, a1.y, a1.z, a1.w};
        float bv[4] = {b.x, b.y, b.z, b.w};
#pragma unroll
        for (int i = 0; i < 8; i++)
#pragma unroll
            for (int j = 0; j < 4; j++)
                acc[i][j] = fmaf(av[i], bv[j], acc[i][j]);
    }

    if (jt == 0) {
        // rows = output channels ty*4..+3 of input projection -> g_xpad
        int o = ty * 4;
        int g = o >> 5, ch = o & 31;
        float4 b4 = *reinterpret_cast<const float4*>(&g_bias[o]);
#pragma unroll
        for (int vi = 0; vi < 8; vi++) {
            int v = vbase + ((vi & 4) << 4) + tx * 4 + (vi & 3);
            int iz = v >> 10, iy = (v >> 5) & 31, ix = v & 31;
            int idx = ((((g * DP + iz + 1) * DP + iy + 1) * DP + ix + 1) << 5) + ch;
            *reinterpret_cast<float4*>(&g_xpad[idx]) =
                make_float4(acc[vi][0] + b4.x, acc[vi][1] + b4.y,
                            acc[vi][2] + b4.z, acc[vi][3] + b4.w);
        }
    } else {
#pragma unroll
        for (int jj = 0; jj < 4; jj++) {
            int j = jt * 64 + ty * 4 + jj;
            float* dst;
            if (j < 226)      dst = g_off  + (j - 64)  * NVOX;
            else if (j < 280) dst = g_mask + (j - 226) * NVOX;
            else continue;
            float bj = g_bias[j];
            *reinterpret_cast<float4*>(dst + vbase + tx * 4) =
                make_float4(acc[0][jj] + bj, acc[1][jj] + bj,
                            acc[2][jj] + bj, acc[3][jj] + bj);
            *reinterpret_cast<float4*>(dst + vbase + 64 + tx * 4) =
                make_float4(acc[4][jj] + bj, acc[5][jj] + bj,
                            acc[6][jj] + bj, acc[7][jj] + bj);
        }
    }
}

// ---------------------------------------------------------------------------
// Kernel 4: deformable trilinear sampling + masked accumulate + output GEMM.
// 16 voxels per block, 256 threads. Softmax over 27 points in smem.
// ---------------------------------------------------------------------------
__global__ void k_sample(const float* __restrict__ out_w, const float* __restrict__ out_b,
                         float* __restrict__ out) {
    int v0 = blockIdx.x * 16;
    int tid = threadIdx.x;
    __shared__ float s_off[16][NOFF];
    __shared__ float s_m[16][NMSK];
    __shared__ float s_acc[16][NC];

    for (int idx = tid; idx < 16 * NOFF; idx += 256) {
        int j = idx >> 4, vloc = idx & 15;
        s_off[vloc][j] = g_off[j * NVOX + v0 + vloc];
    }
    for (int idx = tid; idx < 16 * NMSK; idx += 256) {
        int j = idx >> 4, vloc = idx & 15;
        s_m[vloc][j] = g_mask[j * NVOX + v0 + vloc];
    }
    __syncthreads();

    if (tid < 32) {
        int vv = tid >> 1, gi = tid & 1;
        float* m = &s_m[vv][gi * NP];
        float mx = -1e30f;
#pragma unroll
        for (int p = 0; p < NP; p++) mx = fmaxf(mx, m[p]);
        float s = 0.f;
#pragma unroll
        for (int p = 0; p < NP; p++) { float e = __expf(m[p] - mx); m[p] = e; s += e; }
        float inv = 1.f / s;
#pragma unroll
        for (int p = 0; p < NP; p++) m[p] *= inv;
    }
    __syncthreads();

    int vv = tid >> 4;
    int gi = (tid >> 3) & 1;
    int c4 = tid & 7;
    int v = v0 + vv;
    int iz = v >> 10, iy = (v >> 5) & 31, ix = v & 31;

    const float4* vol = reinterpret_cast<const float4*>(g_xpad) + gi * (VOLG / 4) + c4;
    const float* offp = &s_off[vv][gi * (NP * 3)];
    const float* mp   = &s_m[vv][gi * NP];

    float4 acc = make_float4(0.f, 0.f, 0.f, 0.f);
    for (int p = 0; p < NP; p++) {
        float ox = offp[p * 3 + 0];
        float oy = offp[p * 3 + 1];
        float oz = offp[p * 3 + 2];
        float sx = (float)(ix + (p % 3))       + 0.25f * ox;
        float sy = (float)(iy + ((p / 3) % 3)) + 0.5f  * oy;
        float sz = (float)(iz + (p / 9))       + 0.5f  * oz;
        float xf = floorf(sx), yf = floorf(sy), zf = floorf(sz);
        int x0 = (int)xf, y0 = (int)yf, z0 = (int)zf;
        float fx = sx - xf, fy = sy - yf, fz = sz - zf;

        float4 smp = make_float4(0.f, 0.f, 0.f, 0.f);
#pragma unroll
        for (int dz = 0; dz < 2; dz++) {
            int cz = z0 + dz;
            if ((unsigned)cz >= (unsigned)DP) continue;
            float wz = dz ? fz : 1.f - fz;
#pragma unroll
            for (int dy = 0; dy < 2; dy++) {
                int cy = y0 + dy;
                if ((unsigned)cy >= (unsigned)DP) continue;
                float wy = dy ? fy : 1.f - fy;
#pragma unroll
                for (int dx = 0; dx < 2; dx++) {
                    int cx = x0 + dx;
                    if ((unsigned)cx >= (unsigned)DP) continue;
                    float w = wz * wy * ((dx) ? fx : 1.f - fx);
                    float4 val = vol[((cz * DP + cy) * DP + cx) << 3];
                    smp.x = fmaf(w, val.x, smp.x);
                    smp.y = fmaf(w, val.y, smp.y);
                    smp.z = fmaf(w, val.z, smp.z);
                    smp.w = fmaf(w, val.w, smp.w);
                }
            }
        }
        float m = mp[p];
        acc.x = fmaf(m, smp.x, acc.x);
        acc.y = fmaf(m, smp.y, acc.y);
        acc.z = fmaf(m, smp.z, acc.z);
        acc.w = fmaf(m, smp.w, acc.w);
    }

    int ch = gi * GC + c4 * 4;
    s_acc[vv][ch + 0] = acc.x;
    s_acc[vv][ch + 1] = acc.y;
    s_acc[vv][ch + 2] = acc.z;
    s_acc[vv][ch + 3] = acc.w;
    __syncthreads();

    int vq = tid >> 6;
    int oc = tid & 63;
    float b = __ldg(out_b + oc);
    float o0 = b, o1 = b, o2 = b, o3 = b;
#pragma unroll 8
    for (int c = 0; c < NC; c++) {
        float w = __ldg(out_w + c * NC + oc);
        o0 = fmaf(s_acc[vq * 4 + 0][c], w, o0);
        o1 = fmaf(s_acc[vq * 4 + 1][c], w, o1);
        o2 = fmaf(s_acc[vq * 4 + 2][c], w, o2);
        o3 = fmaf(s_acc[vq * 4 + 3][c], w, o3);
    }
    out[(v0 + vq * 4 + 0) * NC + oc] = o0;
    out[(v0 + vq * 4 + 1) * NC + oc] = o1;
    out[(v0 + vq * 4 + 2) * NC + oc] = o2;
    out[(v0 + vq * 4 + 3) * NC + oc] = o3;
}

// ---------------------------------------------------------------------------
extern "C" void kernel_launch(void* const* d_in, const int* in_sizes, int n_in,
                              void* d_out, int out_size) {
    const float* x      = (const float*)d_in[0];
    const float* dw_w   = (const float*)d_in[1];
    const float* gn_w   = (const float*)d_in[2];
    const float* gn_b   = (const float*)d_in[3];
    const float* inp_w  = (const float*)d_in[4];
    const float* inp_b  = (const float*)d_in[5];
    const float* off_w  = (const float*)d_in[6];
    const float* off_b  = (const float*)d_in[7];
    const float* mask_w = (const float*)d_in[8];
    const float* mask_b = (const float*)d_in[9];
    const float* out_w  = (const float*)d_in[10];
    const float* out_b  = (const float*)d_in[11];
    float* out = (float*)d_out;

    k_init<<<(NC * NJP + 255) / 256, 256>>>(inp_w, off_w, mask_w, inp_b, off_b, mask_b);
    k_dw<<<dim3(32, 64), 256>>>(x, dw_w);
    k_stats<<<1, 256>>>();
    k_point<<<dim3(NVOX / 128, 5), 256>>>(x, gn_w, gn_b);
    k_sample<<<NVOX / 16, 256>>>(out_w, out_b, out);
}